// round 15
// baseline (speedup 1.0000x reference)
#include <cuda_runtime.h>
#include <math.h>
#include <stdint.h>

#define D_MODEL 1024
#define SEQ     2048
#define BATCH   2
#define NH      16
#define HD      64
#define FFN     4096
#define ROWS    (BATCH * SEQ)   /* 4096 */
#define BH      (BATCH * NH)    /* 32 */
#define QKV_LD  (3 * D_MODEL)   /* 3072 */

// ---------------- scratch (static device memory; no allocations) ------------
__device__ float g_qkv[ROWS * QKV_LD];                       // 50 MB
__device__ float g_vals[ROWS * D_MODEL];
__device__ float g_attn[ROWS * D_MODEL];
__device__ float g_h[ROWS * D_MODEL];
__device__ float g_ffn1[(size_t)ROWS * FFN];                 // 64 MB
__device__ float g_ffn2[ROWS * D_MODEL];
// RNA-rounded weight copies (B-side exact in tf32 HW)
__device__ float g_wqkv_r[(size_t)D_MODEL * QKV_LD];
__device__ float g_wo_r[(size_t)D_MODEL * D_MODEL];
__device__ float g_w1_r[(size_t)D_MODEL * FFN];
__device__ float g_w2_r[(size_t)FFN * D_MODEL];

// ---------------- tf32 / async helpers --------------------------------------
__device__ __forceinline__ uint32_t f2tf32(float f) {
    uint32_t u;
    asm("cvt.rna.tf32.f32 %0, %1;" : "=r"(u) : "f"(f));
    return u;
}
__device__ __forceinline__ float round_tf32f(float f) {
    return __uint_as_float(f2tf32(f));
}
// MMA operands fed as raw bits: HW truncates to tf32 (RZ). Inputs that were
// pre-rounded with RNA pass through exactly.
__device__ __forceinline__ void mma_tf32(float* d, const uint32_t* a, const uint32_t* b) {
    asm volatile(
        "mma.sync.aligned.m16n8k8.row.col.f32.tf32.tf32.f32 "
        "{%0,%1,%2,%3}, {%4,%5,%6,%7}, {%8,%9}, {%0,%1,%2,%3};"
        : "+f"(d[0]), "+f"(d[1]), "+f"(d[2]), "+f"(d[3])
        : "r"(a[0]), "r"(a[1]), "r"(a[2]), "r"(a[3]), "r"(b[0]), "r"(b[1]));
}
__device__ __forceinline__ uint32_t smem_u32(const void* p) {
    uint32_t a;
    asm("{ .reg .u64 t; cvta.to.shared.u64 t, %1; cvt.u32.u64 %0, t; }"
        : "=r"(a) : "l"(p));
    return a;
}
__device__ __forceinline__ void cp16(uint32_t dst, const void* src) {
    asm volatile("cp.async.cg.shared.global [%0], [%1], 16;"
                 :: "r"(dst), "l"(src) : "memory");
}
__device__ __forceinline__ void cp_commit() {
    asm volatile("cp.async.commit_group;" ::: "memory");
}
template <int N>
__device__ __forceinline__ void cp_wait() {
    asm volatile("cp.async.wait_group %0;" :: "n"(N) : "memory");
}

// ---------------- weight pre-round: out[i] = RNA_tf32(in[i]) ----------------
__global__ void __launch_bounds__(256) round_w(const float* __restrict__ in,
                                               float* __restrict__ out, int n4) {
    const int i = blockIdx.x * 256 + threadIdx.x;
    if (i < n4) {
        float4 v = ((const float4*)in)[i];
        v.x = round_tf32f(v.x); v.y = round_tf32f(v.y);
        v.z = round_tf32f(v.z); v.w = round_tf32f(v.w);
        ((float4*)out)[i] = v;
    }
}

// ---------------- tf32 GEMM, cp.async 3-stage pipeline ----------------------
// C = A[M,K] @ B[K,N] + bias (opt ReLU, opt RNA-round on write).
// CTA tile 128x128, BK=32, 4 warps (2x2), warp tile 64x64 (4x8 m16n8k8).
// A smem [m][k] str36, B smem [k][n] str136 — conflict-free fragment LDS.
#define AST 36
#define BST 136
#define STG_FLOATS (128 * AST + 32 * BST)     /* 8960 floats = 35840 B */
#define GEMM_SMEM (3 * STG_FLOATS * 4)        /* 107520 B */

template <bool RELU, bool ROUND>
__global__ void __launch_bounds__(128, 2) gemm_mma(const float* __restrict__ A,
                                                   const float* __restrict__ B,
                                                   const float* __restrict__ bias,
                                                   float* __restrict__ C,
                                                   int M, int N, int K) {
    extern __shared__ float smem[];
    const int tid = threadIdx.x;
    const int wid = tid >> 5, lane = tid & 31;
    const int bm = blockIdx.y << 7, bn = blockIdx.x << 7;
    const int wm = (wid >> 1) << 6;          // 0 or 64
    const int wn = (wid & 1) << 6;           // 0 or 64
    const int r = lane >> 2, c = lane & 3;
    const uint32_t smem_base = smem_u32(smem);
    const int NB = K >> 5;

    auto issue = [&](int kb) {
        if (kb < NB) {
            const uint32_t As_b = smem_base + (uint32_t)(kb % 3) * (STG_FLOATS * 4);
            const uint32_t Bs_b = As_b + 128 * AST * 4;
#pragma unroll
            for (int i = 0; i < 8; i++) {
                const int id = tid + (i << 7);
                const int row = id >> 3, kc = (id & 7) << 2;
                cp16(As_b + (uint32_t)(row * AST + kc) * 4,
                     A + (size_t)(bm + row) * K + (kb << 5) + kc);
            }
#pragma unroll
            for (int i = 0; i < 8; i++) {
                const int id = tid + (i << 7);
                const int row = id >> 5, nc = (id & 31) << 2;
                cp16(Bs_b + (uint32_t)(row * BST + nc) * 4,
                     B + (size_t)((kb << 5) + row) * N + bn + nc);
            }
        }
        cp_commit();
    };

    float acc[4][8][4] = {};

    issue(0);
    issue(1);

    for (int kb = 0; kb < NB; kb++) {
        cp_wait<1>();
        __syncthreads();
        issue(kb + 2);

        const float* As_s = smem + (kb % 3) * STG_FLOATS;
        const float* Bs_s = As_s + 128 * AST;
#pragma unroll
        for (int g = 0; g < 4; g++) {
            const int k0 = g << 3;
            uint32_t a[4][4], b[8][2];
#pragma unroll
            for (int mt = 0; mt < 4; mt++) {
                const int m = wm + (mt << 4) + r;
                a[mt][0] = __float_as_uint(As_s[m * AST + k0 + c]);
                a[mt][1] = __float_as_uint(As_s[(m + 8) * AST + k0 + c]);
                a[mt][2] = __float_as_uint(As_s[m * AST + k0 + c + 4]);
                a[mt][3] = __float_as_uint(As_s[(m + 8) * AST + k0 + c + 4]);
            }
#pragma unroll
            for (int nt = 0; nt < 8; nt++) {
                const int n = wn + (nt << 3) + r;
                b[nt][0] = __float_as_uint(Bs_s[(k0 + c) * BST + n]);
                b[nt][1] = __float_as_uint(Bs_s[(k0 + c + 4) * BST + n]);
            }
#pragma unroll
            for (int mt = 0; mt < 4; mt++)
#pragma unroll
                for (int nt = 0; nt < 8; nt++)
                    mma_tf32(acc[mt][nt], a[mt], b[nt]);
        }
    }

    // ---- epilogue: bias (+ReLU) (+RNA round), write C ----
#pragma unroll
    for (int mt = 0; mt < 4; mt++) {
        const int row = bm + wm + (mt << 4) + r;
#pragma unroll
        for (int nt = 0; nt < 8; nt++) {
            const int col = bn + wn + (nt << 3) + (c << 1);
            const float b0 = bias[col], b1 = bias[col + 1];
            float v0 = acc[mt][nt][0] + b0;
            float v1 = acc[mt][nt][1] + b1;
            float v2 = acc[mt][nt][2] + b0;
            float v3 = acc[mt][nt][3] + b1;
            if (RELU) {
                v0 = fmaxf(v0, 0.f); v1 = fmaxf(v1, 0.f);
                v2 = fmaxf(v2, 0.f); v3 = fmaxf(v3, 0.f);
            }
            if (ROUND) {
                v0 = round_tf32f(v0); v1 = round_tf32f(v1);
                v2 = round_tf32f(v2); v3 = round_tf32f(v3);
            }
            *(float2*)&C[(size_t)row * N + col] = make_float2(v0, v1);
            *(float2*)&C[(size_t)(row + 8) * N + col] = make_float2(v2, v3);
        }
    }
}

// ---------------- tf32 tensor-core flash attention ---------------------------
// Per (b,h): 128-row Q tile per CTA, 256 threads (8 warps, warp w owns rows
// 16w..16w+15). K/V streamed in 64-row tiles. Online softmax warp-local.
// Staging uses RNA tf32 rounding; vals written RNA-rounded.
#define ATTN_SMEM ((64 * 136 + 64 * 72 + 64 * 72 + 64 * 136) * 4)
__global__ void __launch_bounds__(256) attn_flash_mma(const float* __restrict__ qkv,
                                                      float* __restrict__ vals) {
    extern __shared__ uint32_t sm[];
    uint32_t* Qs = sm;                    // [64][136]
    uint32_t* Ks = sm + 64 * 136;         // [64][72]
    uint32_t* Vs = Ks + 64 * 72;          // [64][72]
    uint32_t* Ps = Vs + 64 * 72;          // [64][136]

    const int tid = threadIdx.x;
    const int wid = tid >> 5, lane = tid & 31;
    const int r = lane >> 2, c = lane & 3;
    const int z = blockIdx.z, b = z >> 4, h = z & 15;
    const int m0 = blockIdx.y << 7;       // 128-row Q tile
    const size_t base = (size_t)b * SEQ * QKV_LD + (size_t)h * (3 * HD);
    const int wm = wid << 4;              // warp row offset 0..112

    // ---- load Q tile -> Qs[d][m], fold 1/sqrt(64), RNA tf32 ----
    {
        const int row = tid >> 1;
        const int d0 = (tid & 1) << 5;
        const float* Qp = qkv + base + (size_t)(m0 + row) * QKV_LD + d0;
#pragma unroll
        for (int i = 0; i < 8; i++) {
            float4 q = *(const float4*)(Qp + i * 4);
            const int d = d0 + i * 4;
            Qs[(d + 0) * 136 + row] = f2tf32(q.x * 0.125f);
            Qs[(d + 1) * 136 + row] = f2tf32(q.y * 0.125f);
            Qs[(d + 2) * 136 + row] = f2tf32(q.z * 0.125f);
            Qs[(d + 3) * 136 + row] = f2tf32(q.w * 0.125f);
        }
    }

    float m_run[2] = {-1e30f, -1e30f};    // rows wm+r, wm+r+8
    float l_run[2] = {0.f, 0.f};
    float acc[8][4] = {};

    for (int kt = 0; kt < SEQ; kt += 64) {
        __syncthreads();   // prev PV done reading Vs/Ps; Q store visible (it 0)
        // ---- K tile -> Ks[d][n]; V tile -> Vs[k][n] (RNA tf32) ----
        {
            const int row = tid >> 2;            // 0..63
            const int d0 = (tid & 3) << 4;       // 0,16,32,48
            const float* Kp = qkv + base + HD + (size_t)(kt + row) * QKV_LD + d0;
            const float* Vp = qkv + base + 2 * HD + (size_t)(kt + row) * QKV_LD + d0;
#pragma unroll
            for (int i = 0; i < 4; i++) {
                float4 kv = *(const float4*)(Kp + i * 4);
                const int d = d0 + i * 4;
                Ks[(d + 0) * 72 + row] = f2tf32(kv.x);
                Ks[(d + 1) * 72 + row] = f2tf32(kv.y);
                Ks[(d + 2) * 72 + row] = f2tf32(kv.z);
                Ks[(d + 3) * 72 + row] = f2tf32(kv.w);
                float4 vv = *(const float4*)(Vp + i * 4);
                uint4 pv;
                pv.x = f2tf32(vv.x); pv.y = f2tf32(vv.y);
                pv.z = f2tf32(vv.z); pv.w = f2tf32(vv.w);
                *(uint4*)&Vs[row * 72 + d] = pv;
            }
        }
        __syncthreads();

        // ---- S = (Q/8) K^T : warp rows [wm, wm+16), 8 n-tiles ----
        float s[8][4] = {};
#pragma unroll
        for (int k0 = 0; k0 < 64; k0 += 8) {
            uint32_t a[4];
            a[0] = Qs[(k0 + c) * 136 + wm + r];
            a[1] = Qs[(k0 + c) * 136 + wm + r + 8];
            a[2] = Qs[(k0 + c + 4) * 136 + wm + r];
            a[3] = Qs[(k0 + c + 4) * 136 + wm + r + 8];
#pragma unroll
            for (int nt = 0; nt < 8; nt++) {
                uint32_t bf[2];
                bf[0] = Ks[(k0 + c) * 72 + nt * 8 + r];
                bf[1] = Ks[(k0 + c + 4) * 72 + nt * 8 + r];
                mma_tf32(s[nt], a, bf);
            }
        }

        // ---- online softmax (warp-local rows) ----
        float mA = -1e30f, mB = -1e30f;
#pragma unroll
        for (int nt = 0; nt < 8; nt++) {
            mA = fmaxf(mA, fmaxf(s[nt][0], s[nt][1]));
            mB = fmaxf(mB, fmaxf(s[nt][2], s[nt][3]));
        }
        mA = fmaxf(mA, __shfl_xor_sync(0xffffffffu, mA, 1));
        mA = fmaxf(mA, __shfl_xor_sync(0xffffffffu, mA, 2));
        mB = fmaxf(mB, __shfl_xor_sync(0xffffffffu, mB, 1));
        mB = fmaxf(mB, __shfl_xor_sync(0xffffffffu, mB, 2));
        const float mnA = fmaxf(m_run[0], mA);
        const float mnB = fmaxf(m_run[1], mB);
        const float scA = __expf(m_run[0] - mnA);
        const float scB = __expf(m_run[1] - mnB);
        float rsA = 0.f, rsB = 0.f;
#pragma unroll
        for (int nt = 0; nt < 8; nt++) {
            s[nt][0] = __expf(s[nt][0] - mnA);
            s[nt][1] = __expf(s[nt][1] - mnA);
            s[nt][2] = __expf(s[nt][2] - mnB);
            s[nt][3] = __expf(s[nt][3] - mnB);
            rsA += s[nt][0] + s[nt][1];
            rsB += s[nt][2] + s[nt][3];
            acc[nt][0] *= scA; acc[nt][1] *= scA;
            acc[nt][2] *= scB; acc[nt][3] *= scB;
        }
        rsA += __shfl_xor_sync(0xffffffffu, rsA, 1);
        rsA += __shfl_xor_sync(0xffffffffu, rsA, 2);
        rsB += __shfl_xor_sync(0xffffffffu, rsB, 1);
        rsB += __shfl_xor_sync(0xffffffffu, rsB, 2);
        l_run[0] = l_run[0] * scA + rsA;
        l_run[1] = l_run[1] * scB + rsB;
        m_run[0] = mnA;
        m_run[1] = mnB;

        __syncthreads();   // prev PV reads of Ps complete (also K/V read done)

        // ---- stage P -> Ps[k][m] (RNA tf32) ----
#pragma unroll
        for (int nt = 0; nt < 8; nt++) {
            const int n = nt * 8 + (c << 1);
            Ps[(n + 0) * 136 + wm + r]     = f2tf32(s[nt][0]);
            Ps[(n + 1) * 136 + wm + r]     = f2tf32(s[nt][1]);
            Ps[(n + 0) * 136 + wm + r + 8] = f2tf32(s[nt][2]);
            Ps[(n + 1) * 136 + wm + r + 8] = f2tf32(s[nt][3]);
        }
        __syncthreads();

        // ---- O += P @ V ----
#pragma unroll
        for (int k0 = 0; k0 < 64; k0 += 8) {
            uint32_t a[4];
            a[0] = Ps[(k0 + c) * 136 + wm + r];
            a[1] = Ps[(k0 + c) * 136 + wm + r + 8];
            a[2] = Ps[(k0 + c + 4) * 136 + wm + r];
            a[3] = Ps[(k0 + c + 4) * 136 + wm + r + 8];
#pragma unroll
            for (int nt = 0; nt < 8; nt++) {
                uint32_t bf[2];
                bf[0] = Vs[(k0 + c) * 72 + nt * 8 + r];
                bf[1] = Vs[(k0 + c + 4) * 72 + nt * 8 + r];
                mma_tf32(acc[nt], a, bf);
            }
        }
    }

    // ---- finalize: divide by row sums, RNA-round, write [B,S,D] ----
    const float invA = 1.f / l_run[0];
    const float invB = 1.f / l_run[1];
    const size_t rowA = (size_t)(b * SEQ + m0 + wm + r);
    const size_t rowB = rowA + 8;
#pragma unroll
    for (int nt = 0; nt < 8; nt++) {
        const int col = h * HD + nt * 8 + (c << 1);
        *(float2*)&vals[rowA * D_MODEL + col] =
            make_float2(round_tf32f(acc[nt][0] * invA), round_tf32f(acc[nt][1] * invA));
        *(float2*)&vals[rowB * D_MODEL + col] =
            make_float2(round_tf32f(acc[nt][2] * invB), round_tf32f(acc[nt][3] * invB));
    }
}

// ---------------- out = LayerNorm(a + res) ----------------------------------
__global__ void __launch_bounds__(256) add_layernorm(const float* __restrict__ a,
                                                     const float* __restrict__ res,
                                                     const float* __restrict__ gamma,
                                                     const float* __restrict__ beta,
                                                     float* __restrict__ out) {
    __shared__ float smA[8];
    __shared__ float smB[8];
    const int row = blockIdx.x, tid = threadIdx.x;
    const float* pa = a + (size_t)row * D_MODEL;
    const float* pr = res + (size_t)row * D_MODEL;

    float v[4];
    float s = 0.f, sq = 0.f;
#pragma unroll
    for (int i = 0; i < 4; i++) {
        v[i] = pa[tid + (i << 8)] + pr[tid + (i << 8)];
        s += v[i];
        sq += v[i] * v[i];
    }
#pragma unroll
    for (int o = 16; o; o >>= 1) {
        s  += __shfl_xor_sync(0xffffffffu, s, o);
        sq += __shfl_xor_sync(0xffffffffu, sq, o);
    }
    if ((tid & 31) == 0) { smA[tid >> 5] = s; smB[tid >> 5] = sq; }
    __syncthreads();
    s  = smA[0] + smA[1] + smA[2] + smA[3] + smA[4] + smA[5] + smA[6] + smA[7];
    sq = smB[0] + smB[1] + smB[2] + smB[3] + smB[4] + smB[5] + smB[6] + smB[7];

    const float mean = s * (1.f / D_MODEL);
    const float var  = sq * (1.f / D_MODEL) - mean * mean;
    const float rstd = rsqrtf(var + 1e-5f);
#pragma unroll
    for (int i = 0; i < 4; i++) {
        const int c = tid + (i << 8);
        out[(size_t)row * D_MODEL + c] = gamma[c] * (v[i] - mean) * rstd + beta[c];
    }
}

// ---------------- launcher --------------------------------------------------
extern "C" void kernel_launch(void* const* d_in, const int* in_sizes, int n_in,
                              void* d_out, int out_size) {
    const float* x      = (const float*)d_in[0];
    const float* W_qkv  = (const float*)d_in[1];
    const float* b_qkv  = (const float*)d_in[2];
    const float* W_o    = (const float*)d_in[3];
    const float* b_o    = (const float*)d_in[4];
    const float* gamma1 = (const float*)d_in[5];
    const float* beta1  = (const float*)d_in[6];
    const float* W1     = (const float*)d_in[7];
    const float* b1     = (const float*)d_in[8];
    const float* W2     = (const float*)d_in[9];
    const float* b2     = (const float*)d_in[10];
    const float* gamma2 = (const float*)d_in[11];
    const float* beta2  = (const float*)d_in[12];
    float* out = (float*)d_out;

    float *qkv, *vals, *attn, *h, *f1, *f2, *wqkv_r, *wo_r, *w1_r, *w2_r;
    cudaGetSymbolAddress((void**)&qkv,    g_qkv);
    cudaGetSymbolAddress((void**)&vals,   g_vals);
    cudaGetSymbolAddress((void**)&attn,   g_attn);
    cudaGetSymbolAddress((void**)&h,      g_h);
    cudaGetSymbolAddress((void**)&f1,     g_ffn1);
    cudaGetSymbolAddress((void**)&f2,     g_ffn2);
    cudaGetSymbolAddress((void**)&wqkv_r, g_wqkv_r);
    cudaGetSymbolAddress((void**)&wo_r,   g_wo_r);
    cudaGetSymbolAddress((void**)&w1_r,   g_w1_r);
    cudaGetSymbolAddress((void**)&w2_r,   g_w2_r);

    cudaFuncSetAttribute(attn_flash_mma,
                         cudaFuncAttributeMaxDynamicSharedMemorySize, ATTN_SMEM);
    cudaFuncSetAttribute(gemm_mma<false, false>,
                         cudaFuncAttributeMaxDynamicSharedMemorySize, GEMM_SMEM);
    cudaFuncSetAttribute(gemm_mma<true, true>,
                         cudaFuncAttributeMaxDynamicSharedMemorySize, GEMM_SMEM);

    // 0. pre-round weights to tf32 (RNA) — B-side becomes exact in HW
    round_w<<<(D_MODEL * QKV_LD / 4 + 255) / 256, 256>>>(W_qkv, wqkv_r, D_MODEL * QKV_LD / 4);
    round_w<<<(D_MODEL * D_MODEL / 4 + 255) / 256, 256>>>(W_o, wo_r, D_MODEL * D_MODEL / 4);
    round_w<<<(D_MODEL * FFN / 4 + 255) / 256, 256>>>(W1, w1_r, D_MODEL * FFN / 4);
    round_w<<<(FFN * D_MODEL / 4 + 255) / 256, 256>>>(W2, w2_r, FFN * D_MODEL / 4);

    // 1. qkv = x @ W_qkv + b_qkv          [4096, 3072]
    gemm_mma<false, false><<<dim3(QKV_LD / 128, ROWS / 128), 128, GEMM_SMEM>>>(
        x, wqkv_r, b_qkv, qkv, ROWS, QKV_LD, D_MODEL);
    // 2-4. fused attention (tf32 MMA); vals written RNA-rounded
    attn_flash_mma<<<dim3(1, SEQ / 128, BH), 256, ATTN_SMEM>>>(qkv, vals);
    // 5. attn = vals @ W_o + b_o
    gemm_mma<false, false><<<dim3(D_MODEL / 128, ROWS / 128), 128, GEMM_SMEM>>>(
        vals, wo_r, b_o, attn, ROWS, D_MODEL, D_MODEL);
    // 6. h = LN(attn + x)
    add_layernorm<<<ROWS, 256>>>(attn, x, gamma1, beta1, h);
    // 7. f1 = relu(h @ W1 + b1), RNA-rounded on write  [4096, 4096]
    gemm_mma<true, true><<<dim3(FFN / 128, ROWS / 128), 128, GEMM_SMEM>>>(
        h, w1_r, b1, f1, ROWS, FFN, D_MODEL);
    // 8. f2 = f1 @ W2 + b2                [4096, 1024]
    gemm_mma<false, false><<<dim3(D_MODEL / 128, ROWS / 128), 128, GEMM_SMEM>>>(
        f1, w2_r, b2, f2, ROWS, D_MODEL, FFN);
    // 9. out = LN(f2 + h)
    add_layernorm<<<ROWS, 256>>>(f2, h, gamma2, beta2, out);
}

// round 16
// speedup vs baseline: 1.0444x; 1.0444x over previous
#include <cuda_runtime.h>
#include <math.h>
#include <stdint.h>

#define D_MODEL 1024
#define SEQ     2048
#define BATCH   2
#define NH      16
#define HD      64
#define FFN     4096
#define ROWS    (BATCH * SEQ)   /* 4096 */
#define BH      (BATCH * NH)    /* 32 */
#define QKV_LD  (3 * D_MODEL)   /* 3072 */

// ---------------- scratch (static device memory; no allocations) ------------
__device__ float g_qkv[ROWS * QKV_LD];                       // 50 MB
__device__ float g_vals[ROWS * D_MODEL];
__device__ float g_attn[ROWS * D_MODEL];
__device__ float g_h[ROWS * D_MODEL];
__device__ float g_ffn1[(size_t)ROWS * FFN];                 // 64 MB
__device__ float g_ffn2[ROWS * D_MODEL];
// RNA-rounded weight copies (B-side exact in tf32 HW)
__device__ float g_wqkv_r[(size_t)D_MODEL * QKV_LD];
__device__ float g_wo_r[(size_t)D_MODEL * D_MODEL];
__device__ float g_w1_r[(size_t)D_MODEL * FFN];
__device__ float g_w2_r[(size_t)FFN * D_MODEL];

// ---------------- tf32 / async helpers --------------------------------------
__device__ __forceinline__ uint32_t f2tf32(float f) {
    uint32_t u;
    asm("cvt.rna.tf32.f32 %0, %1;" : "=r"(u) : "f"(f));
    return u;
}
__device__ __forceinline__ float round_tf32f(float f) {
    return __uint_as_float(f2tf32(f));
}
// MMA operands fed as raw bits: HW truncates to tf32 (RZ). Inputs that were
// pre-rounded with RNA pass through exactly.
__device__ __forceinline__ void mma_tf32(float* d, const uint32_t* a, const uint32_t* b) {
    asm volatile(
        "mma.sync.aligned.m16n8k8.row.col.f32.tf32.tf32.f32 "
        "{%0,%1,%2,%3}, {%4,%5,%6,%7}, {%8,%9}, {%0,%1,%2,%3};"
        : "+f"(d[0]), "+f"(d[1]), "+f"(d[2]), "+f"(d[3])
        : "r"(a[0]), "r"(a[1]), "r"(a[2]), "r"(a[3]), "r"(b[0]), "r"(b[1]));
}
__device__ __forceinline__ uint32_t smem_u32(const void* p) {
    uint32_t a;
    asm("{ .reg .u64 t; cvta.to.shared.u64 t, %1; cvt.u32.u64 %0, t; }"
        : "=r"(a) : "l"(p));
    return a;
}
__device__ __forceinline__ void cp16(uint32_t dst, const void* src) {
    asm volatile("cp.async.cg.shared.global [%0], [%1], 16;"
                 :: "r"(dst), "l"(src) : "memory");
}
__device__ __forceinline__ void cp_commit() {
    asm volatile("cp.async.commit_group;" ::: "memory");
}
template <int N>
__device__ __forceinline__ void cp_wait() {
    asm volatile("cp.async.wait_group %0;" :: "n"(N) : "memory");
}

// ---------------- weight pre-round: one launch for all four matrices --------
#define N4_QKV (D_MODEL * QKV_LD / 4)   /* 786432  */
#define N4_WO  (D_MODEL * D_MODEL / 4)  /* 262144  */
#define N4_W1  (D_MODEL * FFN / 4)      /* 1048576 */
#define N4_W2  (FFN * D_MODEL / 4)      /* 1048576 */
#define N4_ALL (N4_QKV + N4_WO + N4_W1 + N4_W2)
__global__ void __launch_bounds__(256) round_all(const float* __restrict__ wqkv,
                                                 const float* __restrict__ wo,
                                                 const float* __restrict__ w1,
                                                 const float* __restrict__ w2,
                                                 float* __restrict__ oqkv,
                                                 float* __restrict__ oo,
                                                 float* __restrict__ o1,
                                                 float* __restrict__ o2) {
    int i = blockIdx.x * 256 + threadIdx.x;
    const float4* src;
    float4* dst;
    if (i < N4_QKV) {
        src = (const float4*)wqkv; dst = (float4*)oqkv;
    } else if ((i -= N4_QKV) < N4_WO) {
        src = (const float4*)wo; dst = (float4*)oo;
    } else if ((i -= N4_WO) < N4_W1) {
        src = (const float4*)w1; dst = (float4*)o1;
    } else {
        i -= N4_W1;
        src = (const float4*)w2; dst = (float4*)o2;
    }
    float4 v = src[i];
    v.x = round_tf32f(v.x); v.y = round_tf32f(v.y);
    v.z = round_tf32f(v.z); v.w = round_tf32f(v.w);
    dst[i] = v;
}

// ---------------- tf32 GEMM, cp.async 2-stage pipeline, 3 CTAs/SM -----------
// C = A[M,K] @ B[K,N] + bias (opt ReLU, opt RNA-round on write).
// CTA tile 128x128, BK=32, 4 warps (2x2), warp tile 64x64 (4x8 m16n8k8).
// A smem [m][k] str36, B smem [k][n] str136 — conflict-free fragment LDS.
#define AST 36
#define BST 136
#define STG_FLOATS (128 * AST + 32 * BST)     /* 8960 floats = 35840 B */
#define GEMM_SMEM (2 * STG_FLOATS * 4)        /* 71680 B */

template <bool RELU, bool ROUND>
__global__ void __launch_bounds__(128, 3) gemm_mma(const float* __restrict__ A,
                                                   const float* __restrict__ B,
                                                   const float* __restrict__ bias,
                                                   float* __restrict__ C,
                                                   int M, int N, int K) {
    extern __shared__ float smem[];
    const int tid = threadIdx.x;
    const int wid = tid >> 5, lane = tid & 31;
    const int bm = blockIdx.y << 7, bn = blockIdx.x << 7;
    const int wm = (wid >> 1) << 6;          // 0 or 64
    const int wn = (wid & 1) << 6;           // 0 or 64
    const int r = lane >> 2, c = lane & 3;
    const uint32_t smem_base = smem_u32(smem);
    const int NB = K >> 5;

    auto issue = [&](int kb) {
        if (kb < NB) {
            const uint32_t As_b = smem_base + (uint32_t)(kb & 1) * (STG_FLOATS * 4);
            const uint32_t Bs_b = As_b + 128 * AST * 4;
#pragma unroll
            for (int i = 0; i < 8; i++) {
                const int id = tid + (i << 7);
                const int row = id >> 3, kc = (id & 7) << 2;
                cp16(As_b + (uint32_t)(row * AST + kc) * 4,
                     A + (size_t)(bm + row) * K + (kb << 5) + kc);
            }
#pragma unroll
            for (int i = 0; i < 8; i++) {
                const int id = tid + (i << 7);
                const int row = id >> 5, nc = (id & 31) << 2;
                cp16(Bs_b + (uint32_t)(row * BST + nc) * 4,
                     B + (size_t)((kb << 5) + row) * N + bn + nc);
            }
        }
        cp_commit();
    };

    float acc[4][8][4] = {};

    issue(0);
    issue(1);

    for (int kb = 0; kb < NB; kb++) {
        cp_wait<1>();          // stage kb landed
        __syncthreads();

        const float* As_s = smem + (kb & 1) * STG_FLOATS;
        const float* Bs_s = As_s + 128 * AST;
#pragma unroll
        for (int g = 0; g < 4; g++) {
            const int k0 = g << 3;
            uint32_t a[4][4], b[8][2];
#pragma unroll
            for (int mt = 0; mt < 4; mt++) {
                const int m = wm + (mt << 4) + r;
                a[mt][0] = __float_as_uint(As_s[m * AST + k0 + c]);
                a[mt][1] = __float_as_uint(As_s[(m + 8) * AST + k0 + c]);
                a[mt][2] = __float_as_uint(As_s[m * AST + k0 + c + 4]);
                a[mt][3] = __float_as_uint(As_s[(m + 8) * AST + k0 + c + 4]);
            }
#pragma unroll
            for (int nt = 0; nt < 8; nt++) {
                const int n = wn + (nt << 3) + r;
                b[nt][0] = __float_as_uint(Bs_s[(k0 + c) * BST + n]);
                b[nt][1] = __float_as_uint(Bs_s[(k0 + c + 4) * BST + n]);
            }
#pragma unroll
            for (int mt = 0; mt < 4; mt++)
#pragma unroll
                for (int nt = 0; nt < 8; nt++)
                    mma_tf32(acc[mt][nt], a[mt], b[nt]);
        }

        __syncthreads();       // stage kb fully consumed before refill
        issue(kb + 2);
    }

    // ---- epilogue: bias (+ReLU) (+RNA round), write C ----
#pragma unroll
    for (int mt = 0; mt < 4; mt++) {
        const int row = bm + wm + (mt << 4) + r;
#pragma unroll
        for (int nt = 0; nt < 8; nt++) {
            const int col = bn + wn + (nt << 3) + (c << 1);
            const float b0 = bias[col], b1 = bias[col + 1];
            float v0 = acc[mt][nt][0] + b0;
            float v1 = acc[mt][nt][1] + b1;
            float v2 = acc[mt][nt][2] + b0;
            float v3 = acc[mt][nt][3] + b1;
            if (RELU) {
                v0 = fmaxf(v0, 0.f); v1 = fmaxf(v1, 0.f);
                v2 = fmaxf(v2, 0.f); v3 = fmaxf(v3, 0.f);
            }
            if (ROUND) {
                v0 = round_tf32f(v0); v1 = round_tf32f(v1);
                v2 = round_tf32f(v2); v3 = round_tf32f(v3);
            }
            *(float2*)&C[(size_t)row * N + col] = make_float2(v0, v1);
            *(float2*)&C[(size_t)(row + 8) * N + col] = make_float2(v2, v3);
        }
    }
}

// ---------------- tf32 tensor-core flash attention ---------------------------
// Per (b,h): 128-row Q tile per CTA, 256 threads (8 warps, warp w owns rows
// 16w..16w+15). K/V streamed in 64-row tiles. Online softmax warp-local.
// Staging uses RNA tf32 rounding; vals written RNA-rounded.
#define ATTN_SMEM ((64 * 136 + 64 * 72 + 64 * 72 + 64 * 136) * 4)
__global__ void __launch_bounds__(256) attn_flash_mma(const float* __restrict__ qkv,
                                                      float* __restrict__ vals) {
    extern __shared__ uint32_t sm[];
    uint32_t* Qs = sm;                    // [64][136]
    uint32_t* Ks = sm + 64 * 136;         // [64][72]
    uint32_t* Vs = Ks + 64 * 72;          // [64][72]
    uint32_t* Ps = Vs + 64 * 72;          // [64][136]

    const int tid = threadIdx.x;
    const int wid = tid >> 5, lane = tid & 31;
    const int r = lane >> 2, c = lane & 3;
    const int z = blockIdx.z, b = z >> 4, h = z & 15;
    const int m0 = blockIdx.y << 7;       // 128-row Q tile
    const size_t base = (size_t)b * SEQ * QKV_LD + (size_t)h * (3 * HD);
    const int wm = wid << 4;              // warp row offset 0..112

    // ---- load Q tile -> Qs[d][m], fold 1/sqrt(64), RNA tf32 ----
    {
        const int row = tid >> 1;
        const int d0 = (tid & 1) << 5;
        const float* Qp = qkv + base + (size_t)(m0 + row) * QKV_LD + d0;
#pragma unroll
        for (int i = 0; i < 8; i++) {
            float4 q = *(const float4*)(Qp + i * 4);
            const int d = d0 + i * 4;
            Qs[(d + 0) * 136 + row] = f2tf32(q.x * 0.125f);
            Qs[(d + 1) * 136 + row] = f2tf32(q.y * 0.125f);
            Qs[(d + 2) * 136 + row] = f2tf32(q.z * 0.125f);
            Qs[(d + 3) * 136 + row] = f2tf32(q.w * 0.125f);
        }
    }

    float m_run[2] = {-1e30f, -1e30f};    // rows wm+r, wm+r+8
    float l_run[2] = {0.f, 0.f};
    float acc[8][4] = {};

    for (int kt = 0; kt < SEQ; kt += 64) {
        __syncthreads();   // prev PV done reading Vs/Ps; Q store visible (it 0)
        // ---- K tile -> Ks[d][n]; V tile -> Vs[k][n] (RNA tf32) ----
        {
            const int row = tid >> 2;            // 0..63
            const int d0 = (tid & 3) << 4;       // 0,16,32,48
            const float* Kp = qkv + base + HD + (size_t)(kt + row) * QKV_LD + d0;
            const float* Vp = qkv + base + 2 * HD + (size_t)(kt + row) * QKV_LD + d0;
#pragma unroll
            for (int i = 0; i < 4; i++) {
                float4 kv = *(const float4*)(Kp + i * 4);
                const int d = d0 + i * 4;
                Ks[(d + 0) * 72 + row] = f2tf32(kv.x);
                Ks[(d + 1) * 72 + row] = f2tf32(kv.y);
                Ks[(d + 2) * 72 + row] = f2tf32(kv.z);
                Ks[(d + 3) * 72 + row] = f2tf32(kv.w);
                float4 vv = *(const float4*)(Vp + i * 4);
                uint4 pv;
                pv.x = f2tf32(vv.x); pv.y = f2tf32(vv.y);
                pv.z = f2tf32(vv.z); pv.w = f2tf32(vv.w);
                *(uint4*)&Vs[row * 72 + d] = pv;
            }
        }
        __syncthreads();

        // ---- S = (Q/8) K^T : warp rows [wm, wm+16), 8 n-tiles ----
        float s[8][4] = {};
#pragma unroll
        for (int k0 = 0; k0 < 64; k0 += 8) {
            uint32_t a[4];
            a[0] = Qs[(k0 + c) * 136 + wm + r];
            a[1] = Qs[(k0 + c) * 136 + wm + r + 8];
            a[2] = Qs[(k0 + c + 4) * 136 + wm + r];
            a[3] = Qs[(k0 + c + 4) * 136 + wm + r + 8];
#pragma unroll
            for (int nt = 0; nt < 8; nt++) {
                uint32_t bf[2];
                bf[0] = Ks[(k0 + c) * 72 + nt * 8 + r];
                bf[1] = Ks[(k0 + c + 4) * 72 + nt * 8 + r];
                mma_tf32(s[nt], a, bf);
            }
        }

        // ---- online softmax (warp-local rows) ----
        float mA = -1e30f, mB = -1e30f;
#pragma unroll
        for (int nt = 0; nt < 8; nt++) {
            mA = fmaxf(mA, fmaxf(s[nt][0], s[nt][1]));
            mB = fmaxf(mB, fmaxf(s[nt][2], s[nt][3]));
        }
        mA = fmaxf(mA, __shfl_xor_sync(0xffffffffu, mA, 1));
        mA = fmaxf(mA, __shfl_xor_sync(0xffffffffu, mA, 2));
        mB = fmaxf(mB, __shfl_xor_sync(0xffffffffu, mB, 1));
        mB = fmaxf(mB, __shfl_xor_sync(0xffffffffu, mB, 2));
        const float mnA = fmaxf(m_run[0], mA);
        const float mnB = fmaxf(m_run[1], mB);
        const float scA = __expf(m_run[0] - mnA);
        const float scB = __expf(m_run[1] - mnB);
        float rsA = 0.f, rsB = 0.f;
#pragma unroll
        for (int nt = 0; nt < 8; nt++) {
            s[nt][0] = __expf(s[nt][0] - mnA);
            s[nt][1] = __expf(s[nt][1] - mnA);
            s[nt][2] = __expf(s[nt][2] - mnB);
            s[nt][3] = __expf(s[nt][3] - mnB);
            rsA += s[nt][0] + s[nt][1];
            rsB += s[nt][2] + s[nt][3];
            acc[nt][0] *= scA; acc[nt][1] *= scA;
            acc[nt][2] *= scB; acc[nt][3] *= scB;
        }
        rsA += __shfl_xor_sync(0xffffffffu, rsA, 1);
        rsA += __shfl_xor_sync(0xffffffffu, rsA, 2);
        rsB += __shfl_xor_sync(0xffffffffu, rsB, 1);
        rsB += __shfl_xor_sync(0xffffffffu, rsB, 2);
        l_run[0] = l_run[0] * scA + rsA;
        l_run[1] = l_run[1] * scB + rsB;
        m_run[0] = mnA;
        m_run[1] = mnB;

        __syncthreads();   // prev PV reads of Ps complete (also K/V read done)

        // ---- stage P -> Ps[k][m] (RNA tf32) ----
#pragma unroll
        for (int nt = 0; nt < 8; nt++) {
            const int n = nt * 8 + (c << 1);
            Ps[(n + 0) * 136 + wm + r]     = f2tf32(s[nt][0]);
            Ps[(n + 1) * 136 + wm + r]     = f2tf32(s[nt][1]);
            Ps[(n + 0) * 136 + wm + r + 8] = f2tf32(s[nt][2]);
            Ps[(n + 1) * 136 + wm + r + 8] = f2tf32(s[nt][3]);
        }
        __syncthreads();

        // ---- O += P @ V ----
#pragma unroll
        for (int k0 = 0; k0 < 64; k0 += 8) {
            uint32_t a[4];
            a[0] = Ps[(k0 + c) * 136 + wm + r];
            a[1] = Ps[(k0 + c) * 136 + wm + r + 8];
            a[2] = Ps[(k0 + c + 4) * 136 + wm + r];
            a[3] = Ps[(k0 + c + 4) * 136 + wm + r + 8];
#pragma unroll
            for (int nt = 0; nt < 8; nt++) {
                uint32_t bf[2];
                bf[0] = Vs[(k0 + c) * 72 + nt * 8 + r];
                bf[1] = Vs[(k0 + c + 4) * 72 + nt * 8 + r];
                mma_tf32(acc[nt], a, bf);
            }
        }
    }

    // ---- finalize: divide by row sums, RNA-round, write [B,S,D] ----
    const float invA = 1.f / l_run[0];
    const float invB = 1.f / l_run[1];
    const size_t rowA = (size_t)(b * SEQ + m0 + wm + r);
    const size_t rowB = rowA + 8;
#pragma unroll
    for (int nt = 0; nt < 8; nt++) {
        const int col = h * HD + nt * 8 + (c << 1);
        *(float2*)&vals[rowA * D_MODEL + col] =
            make_float2(round_tf32f(acc[nt][0] * invA), round_tf32f(acc[nt][1] * invA));
        *(float2*)&vals[rowB * D_MODEL + col] =
            make_float2(round_tf32f(acc[nt][2] * invB), round_tf32f(acc[nt][3] * invB));
    }
}

// ---------------- out = LayerNorm(a + res) ----------------------------------
__global__ void __launch_bounds__(256) add_layernorm(const float* __restrict__ a,
                                                     const float* __restrict__ res,
                                                     const float* __restrict__ gamma,
                                                     const float* __restrict__ beta,
                                                     float* __restrict__ out) {
    __shared__ float smA[8];
    __shared__ float smB[8];
    const int row = blockIdx.x, tid = threadIdx.x;
    const float* pa = a + (size_t)row * D_MODEL;
    const float* pr = res + (size_t)row * D_MODEL;

    float v[4];
    float s = 0.f, sq = 0.f;
#pragma unroll
    for (int i = 0; i < 4; i++) {
        v[i] = pa[tid + (i << 8)] + pr[tid + (i << 8)];
        s += v[i];
        sq += v[i] * v[i];
    }
#pragma unroll
    for (int o = 16; o; o >>= 1) {
        s  += __shfl_xor_sync(0xffffffffu, s, o);
        sq += __shfl_xor_sync(0xffffffffu, sq, o);
    }
    if ((tid & 31) == 0) { smA[tid >> 5] = s; smB[tid >> 5] = sq; }
    __syncthreads();
    s  = smA[0] + smA[1] + smA[2] + smA[3] + smA[4] + smA[5] + smA[6] + smA[7];
    sq = smB[0] + smB[1] + smB[2] + smB[3] + smB[4] + smB[5] + smB[6] + smB[7];

    const float mean = s * (1.f / D_MODEL);
    const float var  = sq * (1.f / D_MODEL) - mean * mean;
    const float rstd = rsqrtf(var + 1e-5f);
#pragma unroll
    for (int i = 0; i < 4; i++) {
        const int c = tid + (i << 8);
        out[(size_t)row * D_MODEL + c] = gamma[c] * (v[i] - mean) * rstd + beta[c];
    }
}

// ---------------- launcher --------------------------------------------------
extern "C" void kernel_launch(void* const* d_in, const int* in_sizes, int n_in,
                              void* d_out, int out_size) {
    const float* x      = (const float*)d_in[0];
    const float* W_qkv  = (const float*)d_in[1];
    const float* b_qkv  = (const float*)d_in[2];
    const float* W_o    = (const float*)d_in[3];
    const float* b_o    = (const float*)d_in[4];
    const float* gamma1 = (const float*)d_in[5];
    const float* beta1  = (const float*)d_in[6];
    const float* W1     = (const float*)d_in[7];
    const float* b1     = (const float*)d_in[8];
    const float* W2     = (const float*)d_in[9];
    const float* b2     = (const float*)d_in[10];
    const float* gamma2 = (const float*)d_in[11];
    const float* beta2  = (const float*)d_in[12];
    float* out = (float*)d_out;

    float *qkv, *vals, *attn, *h, *f1, *f2, *wqkv_r, *wo_r, *w1_r, *w2_r;
    cudaGetSymbolAddress((void**)&qkv,    g_qkv);
    cudaGetSymbolAddress((void**)&vals,   g_vals);
    cudaGetSymbolAddress((void**)&attn,   g_attn);
    cudaGetSymbolAddress((void**)&h,      g_h);
    cudaGetSymbolAddress((void**)&f1,     g_ffn1);
    cudaGetSymbolAddress((void**)&f2,     g_ffn2);
    cudaGetSymbolAddress((void**)&wqkv_r, g_wqkv_r);
    cudaGetSymbolAddress((void**)&wo_r,   g_wo_r);
    cudaGetSymbolAddress((void**)&w1_r,   g_w1_r);
    cudaGetSymbolAddress((void**)&w2_r,   g_w2_r);

    cudaFuncSetAttribute(attn_flash_mma,
                         cudaFuncAttributeMaxDynamicSharedMemorySize, ATTN_SMEM);
    cudaFuncSetAttribute(gemm_mma<false, false>,
                         cudaFuncAttributeMaxDynamicSharedMemorySize, GEMM_SMEM);
    cudaFuncSetAttribute(gemm_mma<true, true>,
                         cudaFuncAttributeMaxDynamicSharedMemorySize, GEMM_SMEM);

    // 0. pre-round all weights to tf32 (RNA), single launch
    round_all<<<(N4_ALL + 255) / 256, 256>>>(W_qkv, W_o, W1, W2,
                                             wqkv_r, wo_r, w1_r, w2_r);

    // 1. qkv = x @ W_qkv + b_qkv          [4096, 3072]
    gemm_mma<false, false><<<dim3(QKV_LD / 128, ROWS / 128), 128, GEMM_SMEM>>>(
        x, wqkv_r, b_qkv, qkv, ROWS, QKV_LD, D_MODEL);
    // 2-4. fused attention (tf32 MMA); vals written RNA-rounded
    attn_flash_mma<<<dim3(1, SEQ / 128, BH), 256, ATTN_SMEM>>>(qkv, vals);
    // 5. attn = vals @ W_o + b_o
    gemm_mma<false, false><<<dim3(D_MODEL / 128, ROWS / 128), 128, GEMM_SMEM>>>(
        vals, wo_r, b_o, attn, ROWS, D_MODEL, D_MODEL);
    // 6. h = LN(attn + x)
    add_layernorm<<<ROWS, 256>>>(attn, x, gamma1, beta1, h);
    // 7. f1 = relu(h @ W1 + b1), RNA-rounded on write  [4096, 4096]
    gemm_mma<true, true><<<dim3(FFN / 128, ROWS / 128), 128, GEMM_SMEM>>>(
        h, w1_r, b1, f1, ROWS, FFN, D_MODEL);
    // 8. f2 = f1 @ W2 + b2                [4096, 1024]
    gemm_mma<false, false><<<dim3(D_MODEL / 128, ROWS / 128), 128, GEMM_SMEM>>>(
        f1, w2_r, b2, f2, ROWS, D_MODEL, FFN);
    // 9. out = LN(f2 + h)
    add_layernorm<<<ROWS, 256>>>(f2, h, gamma2, beta2, out);
}